// round 12
// baseline (speedup 1.0000x reference)
#include <cuda_runtime.h>
#include <cuda_bf16.h>
#include <cstdint>

// N=100000 nodes, D=256 features, E=3200000 edges.
#define MAX_N 100000
#define FEAT_D 256

__device__ float g_diag[MAX_N];   // sigmoid(x @ w + b)
__device__ float g_deg[MAX_N];    // degree over col (raw counts)

// ---------------------------------------------------------------------------
// is64 detection: int64 little-endian values < 2^32 have zero odd words.
// ---------------------------------------------------------------------------
__device__ __forceinline__ int detect_is64(const void* eidx) {
    const int* wds = reinterpret_cast<const int*>(eidx);
    int nz = 0;
    #pragma unroll
    for (int i = 0; i < 8; i++) nz |= wds[2 * i + 1];
    return nz == 0;
}

// ---------------------------------------------------------------------------
// K-A: diag[i] = sigmoid(dot(x[i,:], w) + b).
// Two rows per warp, MLP=4 per thread, 512-thread blocks.
// ---------------------------------------------------------------------------
__global__ void diag_kernel(const float* __restrict__ x,
                            const float* __restrict__ w,
                            const float* __restrict__ b,
                            int n) {
    int warp = (blockIdx.x * blockDim.x + threadIdx.x) >> 5;
    int lane = threadIdx.x & 31;
    int row0 = warp * 2;
    if (row0 >= n) return;
    int row1 = row0 + 1;
    bool has1 = (row1 < n);

    const float4* x4 = reinterpret_cast<const float4*>(x);
    const float4* w4 = reinterpret_cast<const float4*>(w);

    float4 a0 = __ldcs(&x4[(size_t)row0 * 64 + lane]);
    float4 a1 = __ldcs(&x4[(size_t)row0 * 64 + lane + 32]);
    float4 c0 = make_float4(0.f, 0.f, 0.f, 0.f);
    float4 c1 = make_float4(0.f, 0.f, 0.f, 0.f);
    if (has1) {
        c0 = __ldcs(&x4[(size_t)row1 * 64 + lane]);
        c1 = __ldcs(&x4[(size_t)row1 * 64 + lane + 32]);
    }
    float4 w0 = __ldg(&w4[lane]);
    float4 w1 = __ldg(&w4[lane + 32]);

    float s0 = a0.x*w0.x + a0.y*w0.y + a0.z*w0.z + a0.w*w0.w
             + a1.x*w1.x + a1.y*w1.y + a1.z*w1.z + a1.w*w1.w;
    float s1 = c0.x*w0.x + c0.y*w0.y + c0.z*w0.z + c0.w*w0.w
             + c1.x*w1.x + c1.y*w1.y + c1.z*w1.z + c1.w*w1.w;

    #pragma unroll
    for (int o = 16; o; o >>= 1) {
        s0 += __shfl_xor_sync(0xFFFFFFFFu, s0, o);
        s1 += __shfl_xor_sync(0xFFFFFFFFu, s1, o);
    }

    if (lane == 0) {
        float bb = __ldg(b);
        g_diag[row0] = 1.0f / (1.0f + expf(-(s0 + bb)));
        if (has1) g_diag[row1] = 1.0f / (1.0f + expf(-(s1 + bb)));
    }
}

// ---------------------------------------------------------------------------
// K-B: degree atomics over col ONLY. 8 edges per thread (atomic MLP=8).
// Reads just the col half of edge_index: 25.6MB instead of 51.2MB, no
// conversion writes. Pure RED throughput + one stream.
// ---------------------------------------------------------------------------
__global__ void deg_kernel(const void* __restrict__ eidx, int E) {
    __shared__ int s_is64;
    if (threadIdx.x == 0) s_is64 = detect_is64(eidx);
    __syncthreads();
    bool is64 = (s_is64 != 0);

    int base = (blockIdx.x * blockDim.x + threadIdx.x) * 8;
    if (base >= E) return;

    if (base + 7 < E) {
        int c[8];
        if (is64) {
            const long long* C = reinterpret_cast<const long long*>(eidx) + E;
            longlong2 c01 = __ldcs(reinterpret_cast<const longlong2*>(C + base));
            longlong2 c23 = __ldcs(reinterpret_cast<const longlong2*>(C + base + 2));
            longlong2 c45 = __ldcs(reinterpret_cast<const longlong2*>(C + base + 4));
            longlong2 c67 = __ldcs(reinterpret_cast<const longlong2*>(C + base + 6));
            c[0]=(int)c01.x; c[1]=(int)c01.y; c[2]=(int)c23.x; c[3]=(int)c23.y;
            c[4]=(int)c45.x; c[5]=(int)c45.y; c[6]=(int)c67.x; c[7]=(int)c67.y;
        } else {
            const int* C = reinterpret_cast<const int*>(eidx) + E;
            int4 a = __ldcs(reinterpret_cast<const int4*>(C + base));
            int4 d = __ldcs(reinterpret_cast<const int4*>(C + base + 4));
            c[0]=a.x; c[1]=a.y; c[2]=a.z; c[3]=a.w;
            c[4]=d.x; c[5]=d.y; c[6]=d.z; c[7]=d.w;
        }
        #pragma unroll
        for (int k = 0; k < 8; k++) atomicAdd(&g_deg[c[k]], 1.0f);
    } else {
        for (int e = base; e < E; e++) {
            int cc = is64 ? (int)reinterpret_cast<const long long*>(eidx)[(size_t)E + e]
                          : reinterpret_cast<const int*>(eidx)[(size_t)E + e];
            atomicAdd(&g_deg[cc], 1.0f);
        }
    }
}

// ---------------------------------------------------------------------------
// K-C: single pass over edges. Reads int64/int32 indices directly, computes
// vals[e] = (1/deg[row]) * attr[e] * diag[col], and (mode3) writes float
// row/col alongside. The 25.6MB intermediate round-trip is gone.
// 8 edges/thread; streaming hints keep L1 for the 800KB gather tables.
// ---------------------------------------------------------------------------
__global__ void val_kernel(const void* __restrict__ eidx,
                           const float* __restrict__ attr,
                           float* __restrict__ out,
                           int E, int mode3) {
    __shared__ int s_is64;
    if (threadIdx.x == 0) s_is64 = detect_is64(eidx);
    __syncthreads();
    bool is64 = (s_is64 != 0);

    int base = (blockIdx.x * blockDim.x + threadIdx.x) * 8;
    if (base >= E) return;
    float* vo = mode3 ? (out + (size_t)2 * E) : out;

    if (base + 7 < E) {
        int r[8], c[8];
        if (is64) {
            const long long* R = reinterpret_cast<const long long*>(eidx);
            const long long* C = R + E;
            longlong2 r01 = __ldcs(reinterpret_cast<const longlong2*>(R + base));
            longlong2 r23 = __ldcs(reinterpret_cast<const longlong2*>(R + base + 2));
            longlong2 r45 = __ldcs(reinterpret_cast<const longlong2*>(R + base + 4));
            longlong2 r67 = __ldcs(reinterpret_cast<const longlong2*>(R + base + 6));
            longlong2 c01 = __ldcs(reinterpret_cast<const longlong2*>(C + base));
            longlong2 c23 = __ldcs(reinterpret_cast<const longlong2*>(C + base + 2));
            longlong2 c45 = __ldcs(reinterpret_cast<const longlong2*>(C + base + 4));
            longlong2 c67 = __ldcs(reinterpret_cast<const longlong2*>(C + base + 6));
            r[0]=(int)r01.x; r[1]=(int)r01.y; r[2]=(int)r23.x; r[3]=(int)r23.y;
            r[4]=(int)r45.x; r[5]=(int)r45.y; r[6]=(int)r67.x; r[7]=(int)r67.y;
            c[0]=(int)c01.x; c[1]=(int)c01.y; c[2]=(int)c23.x; c[3]=(int)c23.y;
            c[4]=(int)c45.x; c[5]=(int)c45.y; c[6]=(int)c67.x; c[7]=(int)c67.y;
        } else {
            const int* R = reinterpret_cast<const int*>(eidx);
            const int* C = R + E;
            int4 ra = __ldcs(reinterpret_cast<const int4*>(R + base));
            int4 rb = __ldcs(reinterpret_cast<const int4*>(R + base + 4));
            int4 ca = __ldcs(reinterpret_cast<const int4*>(C + base));
            int4 cb = __ldcs(reinterpret_cast<const int4*>(C + base + 4));
            r[0]=ra.x; r[1]=ra.y; r[2]=ra.z; r[3]=ra.w;
            r[4]=rb.x; r[5]=rb.y; r[6]=rb.z; r[7]=rb.w;
            c[0]=ca.x; c[1]=ca.y; c[2]=ca.z; c[3]=ca.w;
            c[4]=cb.x; c[5]=cb.y; c[6]=cb.z; c[7]=cb.w;
        }

        const float4* AF = reinterpret_cast<const float4*>(attr + base);
        float4 a0 = __ldcs(AF), a1 = __ldcs(AF + 1);
        float a[8] = {a0.x, a0.y, a0.z, a0.w, a1.x, a1.y, a1.z, a1.w};

        float dr[8], dg[8];
        #pragma unroll
        for (int k = 0; k < 8; k++) dr[k] = __ldg(&g_deg[r[k]]);
        #pragma unroll
        for (int k = 0; k < 8; k++) dg[k] = __ldg(&g_diag[c[k]]);

        float v[8];
        #pragma unroll
        for (int k = 0; k < 8; k++) v[k] = (1.0f / dr[k]) * a[k] * dg[k];

        if (mode3) {
            __stcs(reinterpret_cast<float4*>(out + base),
                   make_float4((float)r[0], (float)r[1], (float)r[2], (float)r[3]));
            __stcs(reinterpret_cast<float4*>(out + base + 4),
                   make_float4((float)r[4], (float)r[5], (float)r[6], (float)r[7]));
            __stcs(reinterpret_cast<float4*>(out + (size_t)E + base),
                   make_float4((float)c[0], (float)c[1], (float)c[2], (float)c[3]));
            __stcs(reinterpret_cast<float4*>(out + (size_t)E + base + 4),
                   make_float4((float)c[4], (float)c[5], (float)c[6], (float)c[7]));
        }
        __stcs(reinterpret_cast<float4*>(vo + base),
               make_float4(v[0], v[1], v[2], v[3]));
        __stcs(reinterpret_cast<float4*>(vo + base + 4),
               make_float4(v[4], v[5], v[6], v[7]));
    } else {
        for (int e = base; e < E; e++) {
            int rr, cc;
            if (is64) {
                rr = (int)reinterpret_cast<const long long*>(eidx)[e];
                cc = (int)reinterpret_cast<const long long*>(eidx)[(size_t)E + e];
            } else {
                rr = reinterpret_cast<const int*>(eidx)[e];
                cc = reinterpret_cast<const int*>(eidx)[(size_t)E + e];
            }
            if (mode3) { out[e] = (float)rr; out[(size_t)E + e] = (float)cc; }
            vo[e] = (1.0f / __ldg(&g_deg[rr])) * attr[e] * __ldg(&g_diag[cc]);
        }
    }
}

// ---------------------------------------------------------------------------
// Launch. Fork kept (aux: memset+deg now ~16us, fits under diag if any
// overlap materializes; harmless if serial):
//   main stream: diag
//   aux  stream: memset(g_deg) -> deg
//   join -> val
// ---------------------------------------------------------------------------
extern "C" void kernel_launch(void* const* d_in, const int* in_sizes, int n_in,
                              void* d_out, int out_size) {
    const float* x    = (const float*)d_in[0];
    const void*  ei   = d_in[1];
    const float* attr = (const float*)d_in[2];
    const float* w    = (const float*)d_in[3];
    const float* b    = (const float*)d_in[4];
    float* out = (float*)d_out;

    int E = in_sizes[2];
    int N = in_sizes[0] / FEAT_D;
    int mode3 = (out_size >= 3 * E) ? 1 : 0;

    static cudaStream_t s_aux = nullptr;
    static cudaEvent_t  ev_fork = nullptr, ev_join = nullptr;
    static void* deg_addr = nullptr;
    if (s_aux == nullptr) {
        cudaStreamCreateWithFlags(&s_aux, cudaStreamNonBlocking);
        cudaEventCreateWithFlags(&ev_fork, cudaEventDisableTiming);
        cudaEventCreateWithFlags(&ev_join, cudaEventDisableTiming);
        cudaGetSymbolAddress(&deg_addr, g_deg);
    }

    cudaEventRecord(ev_fork, 0);
    cudaStreamWaitEvent(s_aux, ev_fork, 0);

    // Branch B (aux): zero degrees, then col-only degree atomics
    cudaMemsetAsync(deg_addr, 0, (size_t)N * sizeof(float), s_aux);
    int dthreads = (E + 7) / 8;
    int dblocks  = (dthreads + 255) / 256;
    deg_kernel<<<dblocks, 256, 0, s_aux>>>(ei, E);
    cudaEventRecord(ev_join, s_aux);

    // Branch A (main): diag, 2 rows per warp, 512-thread blocks
    int diag_warps  = (N + 1) / 2;
    int diag_blocks = (diag_warps + 15) / 16;
    diag_kernel<<<diag_blocks, 512>>>(x, w, b, N);

    // join, then single-pass values (+ index conversion)
    cudaStreamWaitEvent(0, ev_join, 0);
    int vthreads = (E + 7) / 8;
    int vblocks  = (vthreads + 255) / 256;
    val_kernel<<<vblocks, 256>>>(ei, attr, out, E, mode3);
}

// round 14
// speedup vs baseline: 1.0775x; 1.0775x over previous
#include <cuda_runtime.h>
#include <cuda_bf16.h>
#include <cstdint>

// N=100000 nodes, D=256 features, E=3200000 edges.
#define MAX_N 100000
#define MAX_E 3200000
#define FEAT_D 256
#define EDGE_ROLE_BLOCKS 296   // ~2 per SM: persistent atomic pumpers

__device__ float g_diag[MAX_N];   // sigmoid(x @ w + b)
__device__ float g_deg[MAX_N];    // degree over col (raw counts)
// scratch int32 indices, used only when output is values-only (non-mode3)
__device__ int   g_r32[MAX_E];
__device__ int   g_c32[MAX_E];

// ---------------------------------------------------------------------------
// is64 detection: int64 little-endian values < 2^32 have zero odd words.
// ---------------------------------------------------------------------------
__device__ __forceinline__ int detect_is64(const void* eidx) {
    const int* wds = reinterpret_cast<const int*>(eidx);
    int nz = 0;
    #pragma unroll
    for (int i = 0; i < 8; i++) nz |= wds[2 * i + 1];
    return nz == 0;
}

// ---------------------------------------------------------------------------
// Combined kernel, block-role split:
//   bid < EDGE_ROLE_BLOCKS : grid-stride over 1024-edge tiles
//                            (deg atomics + index conversion) — L2-bound
//   else                   : one-shot diag tile of 16 rows     — DRAM-bound
// Edge blocks sit at low blockIdx so they are scheduled first and stay
// resident (~2/SM) while diag blocks stream through the remaining slots.
// ---------------------------------------------------------------------------
__global__ void fused_deg_diag(const float* __restrict__ x,
                               const float* __restrict__ w,
                               const float* __restrict__ b,
                               const void* __restrict__ eidx,
                               float* __restrict__ out,
                               int n, int E, int mode3) {
    const int tid = threadIdx.x;

    if (blockIdx.x < EDGE_ROLE_BLOCKS) {
        // ---------------- edge role: deg atomics + index conversion --------
        __shared__ int s_is64;
        if (tid == 0) s_is64 = detect_is64(eidx);
        __syncthreads();
        const bool is64 = (s_is64 != 0);

        const int tiles = (E + 1023) / 1024;
        for (int tile = blockIdx.x; tile < tiles; tile += EDGE_ROLE_BLOCKS) {
            const int base = tile * 1024 + tid * 4;
            if (base >= E) continue;

            int r[4], c[4];
            if (base + 3 < E) {
                if (is64) {
                    const long long* R = reinterpret_cast<const long long*>(eidx);
                    const long long* C = R + E;
                    longlong2 r01 = __ldcs(reinterpret_cast<const longlong2*>(R + base));
                    longlong2 r23 = __ldcs(reinterpret_cast<const longlong2*>(R + base + 2));
                    longlong2 c01 = __ldcs(reinterpret_cast<const longlong2*>(C + base));
                    longlong2 c23 = __ldcs(reinterpret_cast<const longlong2*>(C + base + 2));
                    r[0]=(int)r01.x; r[1]=(int)r01.y; r[2]=(int)r23.x; r[3]=(int)r23.y;
                    c[0]=(int)c01.x; c[1]=(int)c01.y; c[2]=(int)c23.x; c[3]=(int)c23.y;
                } else {
                    const int* R = reinterpret_cast<const int*>(eidx);
                    const int* C = R + E;
                    int4 ri = __ldcs(reinterpret_cast<const int4*>(R + base));
                    int4 ci = __ldcs(reinterpret_cast<const int4*>(C + base));
                    r[0]=ri.x; r[1]=ri.y; r[2]=ri.z; r[3]=ri.w;
                    c[0]=ci.x; c[1]=ci.y; c[2]=ci.z; c[3]=ci.w;
                }
                #pragma unroll
                for (int k = 0; k < 4; k++) atomicAdd(&g_deg[c[k]], 1.0f);
                if (mode3) {
                    __stcs(reinterpret_cast<float4*>(out + base),
                           make_float4((float)r[0], (float)r[1], (float)r[2], (float)r[3]));
                    __stcs(reinterpret_cast<float4*>(out + (size_t)E + base),
                           make_float4((float)c[0], (float)c[1], (float)c[2], (float)c[3]));
                } else {
                    __stcs(reinterpret_cast<int4*>(g_r32 + base),
                           make_int4(r[0], r[1], r[2], r[3]));
                    __stcs(reinterpret_cast<int4*>(g_c32 + base),
                           make_int4(c[0], c[1], c[2], c[3]));
                }
            } else {
                for (int e = base; e < E; e++) {
                    int rr, cc;
                    if (is64) {
                        rr = (int)reinterpret_cast<const long long*>(eidx)[e];
                        cc = (int)reinterpret_cast<const long long*>(eidx)[(size_t)E + e];
                    } else {
                        rr = reinterpret_cast<const int*>(eidx)[e];
                        cc = reinterpret_cast<const int*>(eidx)[(size_t)E + e];
                    }
                    atomicAdd(&g_deg[cc], 1.0f);
                    if (mode3) { out[e] = (float)rr; out[(size_t)E + e] = (float)cc; }
                    else       { g_r32[e] = rr; g_c32[e] = cc; }
                }
            }
        }
    } else {
        // ---------------- diag role: 16 rows per block, 2 rows per warp ----
        const int db   = blockIdx.x - EDGE_ROLE_BLOCKS;
        const int lane = tid & 31;
        const int wrp  = tid >> 5;
        const int row0 = db * 16 + wrp * 2;
        if (row0 >= n) return;
        const int row1 = row0 + 1;
        const bool has1 = (row1 < n);

        const float4* x4 = reinterpret_cast<const float4*>(x);
        const float4* w4 = reinterpret_cast<const float4*>(w);

        float4 a0 = __ldcs(&x4[(size_t)row0 * 64 + lane]);
        float4 a1 = __ldcs(&x4[(size_t)row0 * 64 + lane + 32]);
        float4 c0 = make_float4(0.f, 0.f, 0.f, 0.f);
        float4 c1 = make_float4(0.f, 0.f, 0.f, 0.f);
        if (has1) {
            c0 = __ldcs(&x4[(size_t)row1 * 64 + lane]);
            c1 = __ldcs(&x4[(size_t)row1 * 64 + lane + 32]);
        }
        float4 w0 = __ldg(&w4[lane]);
        float4 w1 = __ldg(&w4[lane + 32]);

        float s0 = a0.x*w0.x + a0.y*w0.y + a0.z*w0.z + a0.w*w0.w
                 + a1.x*w1.x + a1.y*w1.y + a1.z*w1.z + a1.w*w1.w;
        float s1 = c0.x*w0.x + c0.y*w0.y + c0.z*w0.z + c0.w*w0.w
                 + c1.x*w1.x + c1.y*w1.y + c1.z*w1.z + c1.w*w1.w;

        #pragma unroll
        for (int o = 16; o; o >>= 1) {
            s0 += __shfl_xor_sync(0xFFFFFFFFu, s0, o);
            s1 += __shfl_xor_sync(0xFFFFFFFFu, s1, o);
        }

        if (lane == 0) {
            float bb = __ldg(b);
            g_diag[row0] = 1.0f / (1.0f + expf(-(s0 + bb)));
            if (has1) g_diag[row1] = 1.0f / (1.0f + expf(-(s1 + bb)));
        }
    }
}

// ---------------------------------------------------------------------------
// val: vals[e] = (1/deg[row]) * attr[e] * diag[col]. 8 edges/thread.
// Reads converted indices coalesced (float in out / int32 scratch);
// streaming hints keep L1 for the 800KB gather tables.
// ---------------------------------------------------------------------------
__global__ void val_kernel(const float* __restrict__ attr,
                           float* __restrict__ out,
                           int E, int mode3) {
    int base = (blockIdx.x * blockDim.x + threadIdx.x) * 8;
    if (base >= E) return;
    float* vo = mode3 ? (out + (size_t)2 * E) : out;

    if (base + 7 < E) {
        int r[8], c[8];
        if (mode3) {
            const float4* RF = reinterpret_cast<const float4*>(out + base);
            const float4* CF = reinterpret_cast<const float4*>(out + (size_t)E + base);
            float4 r0 = __ldcs(RF), r1 = __ldcs(RF + 1);
            float4 c0 = __ldcs(CF), c1 = __ldcs(CF + 1);
            r[0]=(int)r0.x; r[1]=(int)r0.y; r[2]=(int)r0.z; r[3]=(int)r0.w;
            r[4]=(int)r1.x; r[5]=(int)r1.y; r[6]=(int)r1.z; r[7]=(int)r1.w;
            c[0]=(int)c0.x; c[1]=(int)c0.y; c[2]=(int)c0.z; c[3]=(int)c0.w;
            c[4]=(int)c1.x; c[5]=(int)c1.y; c[6]=(int)c1.z; c[7]=(int)c1.w;
        } else {
            const int4* RI = reinterpret_cast<const int4*>(g_r32 + base);
            const int4* CI = reinterpret_cast<const int4*>(g_c32 + base);
            int4 r0 = __ldcs(RI), r1 = __ldcs(RI + 1);
            int4 c0 = __ldcs(CI), c1 = __ldcs(CI + 1);
            r[0]=r0.x; r[1]=r0.y; r[2]=r0.z; r[3]=r0.w;
            r[4]=r1.x; r[5]=r1.y; r[6]=r1.z; r[7]=r1.w;
            c[0]=c0.x; c[1]=c0.y; c[2]=c0.z; c[3]=c0.w;
            c[4]=c1.x; c[5]=c1.y; c[6]=c1.z; c[7]=c1.w;
        }

        const float4* AF = reinterpret_cast<const float4*>(attr + base);
        float4 a0 = __ldcs(AF), a1 = __ldcs(AF + 1);
        float a[8] = {a0.x, a0.y, a0.z, a0.w, a1.x, a1.y, a1.z, a1.w};

        float dr[8], dg[8];
        #pragma unroll
        for (int k = 0; k < 8; k++) dr[k] = __ldg(&g_deg[r[k]]);
        #pragma unroll
        for (int k = 0; k < 8; k++) dg[k] = __ldg(&g_diag[c[k]]);

        float v[8];
        #pragma unroll
        for (int k = 0; k < 8; k++) v[k] = (1.0f / dr[k]) * a[k] * dg[k];

        __stcs(reinterpret_cast<float4*>(vo + base),
               make_float4(v[0], v[1], v[2], v[3]));
        __stcs(reinterpret_cast<float4*>(vo + base + 4),
               make_float4(v[4], v[5], v[6], v[7]));
    } else {
        for (int e = base; e < E; e++) {
            int rr = mode3 ? (int)out[e] : g_r32[e];
            int cc = mode3 ? (int)out[(size_t)E + e] : g_c32[e];
            vo[e] = (1.0f / __ldg(&g_deg[rr])) * attr[e] * __ldg(&g_diag[cc]);
        }
    }
}

// ---------------------------------------------------------------------------
// Launch: memset -> combined deg+diag -> val. Single stream, 3 graph nodes.
// ---------------------------------------------------------------------------
extern "C" void kernel_launch(void* const* d_in, const int* in_sizes, int n_in,
                              void* d_out, int out_size) {
    const float* x    = (const float*)d_in[0];
    const void*  ei   = d_in[1];
    const float* attr = (const float*)d_in[2];
    const float* w    = (const float*)d_in[3];
    const float* b    = (const float*)d_in[4];
    float* out = (float*)d_out;

    int E = in_sizes[2];
    int N = in_sizes[0] / FEAT_D;
    int mode3 = (out_size >= 3 * E) ? 1 : 0;

    static void* deg_addr = nullptr;
    if (deg_addr == nullptr) cudaGetSymbolAddress(&deg_addr, g_deg);

    // zero degree counts
    cudaMemsetAsync(deg_addr, 0, (size_t)N * sizeof(float), 0);

    // combined: 296 persistent edge blocks + one-shot diag blocks
    int diag_blocks = (N + 15) / 16;                 // 6250
    int grid = EDGE_ROLE_BLOCKS + diag_blocks;
    fused_deg_diag<<<grid, 256>>>(x, w, b, ei, out, N, E, mode3);

    // values
    int vthreads = (E + 7) / 8;
    int vblocks  = (vthreads + 255) / 256;
    val_kernel<<<vblocks, 256>>>(attr, out, E, mode3);
}